// round 3
// baseline (speedup 1.0000x reference)
#include <cuda_runtime.h>

#define N_ROWS 262144
#define DIM 64
#define KCODES 512
#define ROWS_PER_CTA 128
#define NCTA (N_ROWS / ROWS_PER_CTA)   /* 2048 */
#define THREADS 256

// smem layout (floats): Ws[64][512] | Xs[64][128] | w2s[512] | Ss[128] | red[256] | bidx[128]
#define SMEM_FLOATS (64*512 + 64*128 + 512 + 128 + 256 + 128)
#define SMEM_BYTES (SMEM_FLOATS * 4)

__device__ float g_w2[KCODES];
__device__ int   g_counts[KCODES];
__device__ float g_partials[NCTA];

// ---------------------------------------------------------------------------
// Prep: codebook squared norms + zero histogram (re-zeroed every launch so the
// kernel is graph-replay deterministic).
// ---------------------------------------------------------------------------
__global__ void vq_prep(const float* __restrict__ W) {
    int k = threadIdx.x;
    const float* w = W + k * DIM;
    float s = 0.f;
    #pragma unroll
    for (int d = 0; d < DIM; ++d) s += w[d] * w[d];
    g_w2[k] = s;
    g_counts[k] = 0;
}

// ---------------------------------------------------------------------------
// Main: fused GEMM + argmin + gather + partial MSE + histogram
// ---------------------------------------------------------------------------
__global__ __launch_bounds__(THREADS, 1)
void vq_main(const float* __restrict__ X, const float* __restrict__ W,
             float* __restrict__ out)
{
    extern __shared__ float smem[];
    float* Ws    = smem;                  // [64][512] d-major
    float* Xs    = Ws + 64 * 512;         // [64][128] d-major
    float* w2s   = Xs + 64 * 128;         // [512]
    float* Ss    = w2s + 512;             // [128]
    float* redf  = Ss + 128;              // [256]
    int*   bidxs = (int*)(redf + 256);    // [128]

    const int tid = threadIdx.x;
    const int tx = tid & 15, ty = tid >> 4;
    const int bid = blockIdx.x;
    const size_t row0 = (size_t)bid * ROWS_PER_CTA;

    // --- stage W transposed into smem (conflict-free stores: lanes vary k) ---
    const float4* Wg4 = (const float4*)W;
    for (int i = tid; i < KCODES * 16; i += THREADS) {
        int k = i & (KCODES - 1), d4 = i >> 9;
        float4 v = Wg4[k * 16 + d4];
        Ws[(d4 * 4 + 0) * 512 + k] = v.x;
        Ws[(d4 * 4 + 1) * 512 + k] = v.y;
        Ws[(d4 * 4 + 2) * 512 + k] = v.z;
        Ws[(d4 * 4 + 3) * 512 + k] = v.w;
    }
    for (int i = tid; i < KCODES; i += THREADS) w2s[i] = g_w2[i];

    // --- stage X tile transposed (lanes vary r -> conflict-free stores) ---
    const float4* Xg4 = (const float4*)(X + row0 * DIM);
    for (int i = tid; i < ROWS_PER_CTA * 16; i += THREADS) {
        int r = i & 127, d4 = i >> 7;
        float4 v = Xg4[r * 16 + d4];
        Xs[(d4 * 4 + 0) * 128 + r] = v.x;
        Xs[(d4 * 4 + 1) * 128 + r] = v.y;
        Xs[(d4 * 4 + 2) * 128 + r] = v.z;
        Xs[(d4 * 4 + 3) * 128 + r] = v.w;
    }
    __syncthreads();

    // --- per-row ||x||^2 (sequential over d, matching reference's sum order
    //     up to grid-shift tolerance) ---
    if (tid < ROWS_PER_CTA) {
        float s = 0.f;
        #pragma unroll
        for (int d = 0; d < DIM; ++d) { float x = Xs[d * 128 + tid]; s += x * x; }
        Ss[tid] = s;
    }
    __syncthreads();

    float S[8];
    #pragma unroll
    for (int i = 0; i < 8; ++i) S[i] = Ss[ty * 8 + i];

    float best[8]; int bidx[8];
    #pragma unroll
    for (int i = 0; i < 8; ++i) { best[i] = 3.4e38f; bidx[i] = 0; }

    const float4* Xs4 = (const float4*)Xs;
    const float4* Ws4 = (const float4*)Ws;
    const int ty2 = ty * 2, tx2 = tx * 2;

    #pragma unroll 1
    for (int c = 0; c < 4; ++c) {
        float acc[8][8];
        #pragma unroll
        for (int i = 0; i < 8; ++i)
            #pragma unroll
            for (int j = 0; j < 8; ++j) acc[i][j] = 0.f;

        const int cb = c * 128, cb4 = c * 32;
        #pragma unroll 8
        for (int d = 0; d < DIM; ++d) {
            float4 a0 = Xs4[d * 32 + ty2];
            float4 a1 = Xs4[d * 32 + ty2 + 1];
            float4 b0 = Ws4[d * 128 + cb4 + tx2];
            float4 b1 = Ws4[d * 128 + cb4 + tx2 + 1];
            float a[8] = {a0.x, a0.y, a0.z, a0.w, a1.x, a1.y, a1.z, a1.w};
            float b[8] = {b0.x, b0.y, b0.z, b0.w, b1.x, b1.y, b1.z, b1.w};
            #pragma unroll
            for (int i = 0; i < 8; ++i)
                #pragma unroll
                for (int j = 0; j < 8; ++j) acc[i][j] += a[i] * b[j];
        }

        // dist replicates reference rounding: fl(fl(S + w2) - 2*dot)
        #pragma unroll
        for (int j = 0; j < 8; ++j) {
            int col = cb + tx * 8 + j;
            float w2c = w2s[col];
            #pragma unroll
            for (int i = 0; i < 8; ++i) {
                float t1 = S[i] + w2c;
                float dist = t1 - 2.0f * acc[i][j];  // fl(2a)=2a exact -> FMA-safe
                if (dist < best[i]) { best[i] = dist; bidx[i] = col; }  // first-min
            }
        }
    }

    // --- argmin reduce across the 16 tx-threads (within half-warps) ---
    #pragma unroll
    for (int i = 0; i < 8; ++i) {
        #pragma unroll
        for (int off = 8; off > 0; off >>= 1) {
            float ov = __shfl_xor_sync(0xffffffffu, best[i], off);
            int   oi = __shfl_xor_sync(0xffffffffu, bidx[i], off);
            if (ov < best[i] || (ov == best[i] && oi < bidx[i])) {
                best[i] = ov; bidx[i] = oi;
            }
        }
    }
    if (tx == 0) {
        #pragma unroll
        for (int i = 0; i < 8; ++i) bidxs[ty * 8 + i] = bidx[i];
    }
    __syncthreads();

    // --- outputs: layout [loss | quantized N*64 | perplexity | indices N] ---
    // out_q = out + 1 is only 4B-aligned -> quantized stores MUST be scalar
    // STG.32 (a float4 store here trapped with "misaligned address" in R1).
    float* out_q = out + 1;
    float* out_i = out + 2 + (size_t)N_ROWS * DIM;

    if (tid < ROWS_PER_CTA) {
        int k = bidxs[tid];
        out_i[row0 + tid] = (float)k;
        atomicAdd(&g_counts[k], 1);
    }

    float sq = 0.f;
    for (int i = tid; i < ROWS_PER_CTA * 16; i += THREADS) {
        int r = i & 127, d4 = i >> 7;
        int k = bidxs[r];
        float4 qv, xv;
        qv.x = Ws[(d4 * 4 + 0) * 512 + k];  xv.x = Xs[(d4 * 4 + 0) * 128 + r];
        qv.y = Ws[(d4 * 4 + 1) * 512 + k];  xv.y = Xs[(d4 * 4 + 1) * 128 + r];
        qv.z = Ws[(d4 * 4 + 2) * 512 + k];  xv.z = Xs[(d4 * 4 + 2) * 128 + r];
        qv.w = Ws[(d4 * 4 + 3) * 512 + k];  xv.w = Xs[(d4 * 4 + 3) * 128 + r];
        float* dst = out_q + (row0 + r) * DIM + d4 * 4;
        dst[0] = qv.x;  dst[1] = qv.y;  dst[2] = qv.z;  dst[3] = qv.w;
        float dx = qv.x - xv.x, dy = qv.y - xv.y;
        float dz = qv.z - xv.z, dw = qv.w - xv.w;
        sq += dx * dx + dy * dy + dz * dz + dw * dw;
    }

    redf[tid] = sq;
    __syncthreads();
    #pragma unroll
    for (int s = THREADS / 2; s > 0; s >>= 1) {
        if (tid < s) redf[tid] += redf[tid + s];
        __syncthreads();
    }
    if (tid == 0) g_partials[bid] = redf[0];
}

// ---------------------------------------------------------------------------
// Final: deterministic scalar reductions -> loss, perplexity
// ---------------------------------------------------------------------------
__global__ void vq_final(float* __restrict__ out) {
    __shared__ float sh[KCODES];
    int t = threadIdx.x;

    float p = (float)g_counts[t] * (1.0f / (float)N_ROWS);
    sh[t] = -p * logf(p + 1e-10f);
    __syncthreads();
    for (int s = KCODES / 2; s > 0; s >>= 1) {
        if (t < s) sh[t] += sh[t + s];
        __syncthreads();
    }
    float ent = sh[0];
    __syncthreads();

    float ps = 0.f;
    for (int i = t; i < NCTA; i += KCODES) ps += g_partials[i];
    sh[t] = ps;
    __syncthreads();
    for (int s = KCODES / 2; s > 0; s >>= 1) {
        if (t < s) sh[t] += sh[t + s];
        __syncthreads();
    }
    if (t == 0) {
        float mse = sh[0] / (float)((size_t)N_ROWS * DIM);
        out[0] = 1.25f * mse;                              // q_loss + 0.25*e_loss
        out[1 + (size_t)N_ROWS * DIM] = expf(ent) / (float)KCODES;
    }
}

// ---------------------------------------------------------------------------
extern "C" void kernel_launch(void* const* d_in, const int* in_sizes, int n_in,
                              void* d_out, int out_size)
{
    const float* X = (const float*)d_in[0];
    const float* W = (const float*)d_in[1];
    if (n_in >= 2 && in_sizes[0] == KCODES * DIM) {  // defensive input-order check
        X = (const float*)d_in[1];
        W = (const float*)d_in[0];
    }
    float* out = (float*)d_out;
    (void)out_size;

    cudaFuncSetAttribute(vq_main, cudaFuncAttributeMaxDynamicSharedMemorySize,
                         SMEM_BYTES);

    vq_prep<<<1, KCODES>>>(W);
    vq_main<<<NCTA, THREADS, SMEM_BYTES>>>(X, W, out);
    vq_final<<<1, KCODES>>>(out);
}

// round 4
// speedup vs baseline: 1.7281x; 1.7281x over previous
#include <cuda_runtime.h>

#define N_ROWS 262144
#define DIM 64
#define KCODES 512
#define ROWS_PER_CTA 256
#define NCTA (N_ROWS / ROWS_PER_CTA)   /* 1024 */
#define THREADS 512

// smem layout (floats):
//   Ws[64][512] | Xs[64][256] | w2s[512] | Ss[256] | red[512] | bidx[256]
#define SMEM_FLOATS (64*512 + 64*256 + 512 + 256 + 512 + 256)
#define SMEM_BYTES (SMEM_FLOATS * 4)

__device__ int   g_counts[KCODES];
__device__ float g_partials[NCTA];

// packed f32x2 helpers (Blackwell PTX; ptxas never emits FFMA2 from C++)
#define PACK_F32X2(out, lo, hi) \
    asm("mov.b64 %0, {%1, %2};" : "=l"(out) : "f"(lo), "f"(hi))
#define UNPACK_F32X2(lo, hi, in) \
    asm("mov.b64 {%0, %1}, %2;" : "=f"(lo), "=f"(hi) : "l"(in))
#define FMA_F32X2(d, a, b, c) \
    asm("fma.rn.f32x2 %0, %1, %2, %3;" : "=l"(d) : "l"(a), "l"(b), "l"(c))

// ---------------------------------------------------------------------------
// Prep: zero histogram only (graph-replay determinism). W-norms moved into
// vq_main (R3 ncu: this kernel cost 30us doing serial DRAM reads).
// ---------------------------------------------------------------------------
__global__ void vq_prep() {
    g_counts[threadIdx.x] = 0;
}

// ---------------------------------------------------------------------------
// Main: fused GEMM(FFMA2) + argmin + gather + partial MSE + histogram
// ---------------------------------------------------------------------------
__global__ __launch_bounds__(THREADS, 1)
void vq_main(const float* __restrict__ X, const float* __restrict__ W,
             float* __restrict__ out)
{
    extern __shared__ float smem[];
    float* Ws    = smem;                  // [64][512] d-major
    float* Xs    = Ws + 64 * 512;         // [64][256] d-major
    float* w2s   = Xs + 64 * 256;         // [512]
    float* Ss    = w2s + 512;             // [256]
    float* redf  = Ss + 256;              // [512]
    int*   bidxs = (int*)(redf + 512);    // [256]

    const int tid = threadIdx.x;
    const int tx = tid & 15, ty = tid >> 4;          // 16 x 32 thread grid
    const int bid = blockIdx.x;
    const size_t row0 = (size_t)bid * ROWS_PER_CTA;

    // --- stage W transposed into smem ---
    const float4* Wg4 = (const float4*)W;
    for (int i = tid; i < KCODES * 16; i += THREADS) {
        int k = i & (KCODES - 1), d4 = i >> 9;
        float4 v = Wg4[k * 16 + d4];
        Ws[(d4 * 4 + 0) * 512 + k] = v.x;
        Ws[(d4 * 4 + 1) * 512 + k] = v.y;
        Ws[(d4 * 4 + 2) * 512 + k] = v.z;
        Ws[(d4 * 4 + 3) * 512 + k] = v.w;
    }

    // --- stage X tile transposed ---
    const float4* Xg4 = (const float4*)(X + row0 * DIM);
    for (int i = tid; i < ROWS_PER_CTA * 16; i += THREADS) {
        int r = i & 255, d4 = i >> 8;
        float4 v = Xg4[r * 16 + d4];
        Xs[(d4 * 4 + 0) * 256 + r] = v.x;
        Xs[(d4 * 4 + 1) * 256 + r] = v.y;
        Xs[(d4 * 4 + 2) * 256 + r] = v.z;
        Xs[(d4 * 4 + 3) * 256 + r] = v.w;
    }
    __syncthreads();

    // --- codebook norms: one thread per code, sequential d (bit-identical to
    //     the previously passing vq_prep order) ---
    {
        float s = 0.f;
        #pragma unroll
        for (int d = 0; d < DIM; ++d) { float w = Ws[d * 512 + tid]; s += w * w; }
        w2s[tid] = s;
    }

    // --- per-row ||x||^2, sequential d ---
    if (tid < ROWS_PER_CTA) {
        float s = 0.f;
        #pragma unroll
        for (int d = 0; d < DIM; ++d) { float x = Xs[d * 256 + tid]; s += x * x; }
        Ss[tid] = s;
    }
    __syncthreads();

    float S[8];
    #pragma unroll
    for (int i = 0; i < 8; ++i) S[i] = Ss[ty * 8 + i];

    float best[8]; int bidx[8];
    #pragma unroll
    for (int i = 0; i < 8; ++i) { best[i] = 3.4e38f; bidx[i] = 0; }

    const float4* Xs4 = (const float4*)Xs;
    const float4* Ws4 = (const float4*)Ws;
    const int ty2 = ty * 2, tx2 = tx * 2;

    #pragma unroll 1
    for (int c = 0; c < 4; ++c) {
        // acc pairs over ROWS: acc2[i2][j] = (dot[2*i2][j], dot[2*i2+1][j])
        unsigned long long acc2[4][8];
        #pragma unroll
        for (int i2 = 0; i2 < 4; ++i2)
            #pragma unroll
            for (int j = 0; j < 8; ++j) acc2[i2][j] = 0ull;

        const int cb = c * 128, cb4 = c * 32;
        #pragma unroll 4
        for (int d = 0; d < DIM; ++d) {
            float4 a0 = Xs4[d * 64 + ty2];        // rows ty*8 .. +3
            float4 a1 = Xs4[d * 64 + ty2 + 1];    // rows ty*8+4 .. +7
            float4 b0 = Ws4[d * 128 + cb4 + tx2];
            float4 b1 = Ws4[d * 128 + cb4 + tx2 + 1];

            unsigned long long a2[4];             // row pairs (free: LDS.128 quads)
            PACK_F32X2(a2[0], a0.x, a0.y);
            PACK_F32X2(a2[1], a0.z, a0.w);
            PACK_F32X2(a2[2], a1.x, a1.y);
            PACK_F32X2(a2[3], a1.z, a1.w);

            float b[8] = {b0.x, b0.y, b0.z, b0.w, b1.x, b1.y, b1.z, b1.w};
            #pragma unroll
            for (int j = 0; j < 8; ++j) {
                unsigned long long b2;            // column broadcast
                PACK_F32X2(b2, b[j], b[j]);
                #pragma unroll
                for (int i2 = 0; i2 < 4; ++i2)
                    FMA_F32X2(acc2[i2][j], a2[i2], b2, acc2[i2][j]);
            }
        }

        // dist replicates reference rounding: fl(fl(S + w2) - 2*dot)
        #pragma unroll
        for (int j = 0; j < 8; ++j) {
            int col = cb + tx * 8 + j;
            float w2c = w2s[col];
            #pragma unroll
            for (int i2 = 0; i2 < 4; ++i2) {
                float dlo, dhi;
                UNPACK_F32X2(dlo, dhi, acc2[i2][j]);
                int i = i2 * 2;
                float t1 = S[i] + w2c;
                float dist = t1 - 2.0f * dlo;     // fl(2a)=2a exact -> FMA-safe
                if (dist < best[i]) { best[i] = dist; bidx[i] = col; }
                float t1b = S[i + 1] + w2c;
                float distb = t1b - 2.0f * dhi;
                if (distb < best[i + 1]) { best[i + 1] = distb; bidx[i + 1] = col; }
            }
        }
    }

    // --- argmin reduce across the 16 tx-threads (within half-warps) ---
    #pragma unroll
    for (int i = 0; i < 8; ++i) {
        #pragma unroll
        for (int off = 8; off > 0; off >>= 1) {
            float ov = __shfl_xor_sync(0xffffffffu, best[i], off);
            int   oi = __shfl_xor_sync(0xffffffffu, bidx[i], off);
            if (ov < best[i] || (ov == best[i] && oi < bidx[i])) {
                best[i] = ov; bidx[i] = oi;
            }
        }
    }
    if (tx == 0) {
        #pragma unroll
        for (int i = 0; i < 8; ++i) bidxs[ty * 8 + i] = bidx[i];
    }
    __syncthreads();

    // --- outputs: layout [loss | quantized N*64 | perplexity | indices N] ---
    // out_q = out + 1 is only 4B-aligned -> quantized stores MUST be STG.32.
    float* out_q = out + 1;
    float* out_i = out + 2 + (size_t)N_ROWS * DIM;

    if (tid < ROWS_PER_CTA) {
        int k = bidxs[tid];
        out_i[row0 + tid] = (float)k;
        atomicAdd(&g_counts[k], 1);
    }

    float sq = 0.f;
    for (int i = tid; i < ROWS_PER_CTA * 16; i += THREADS) {
        int r = i & 255, d4 = i >> 8;
        int k = bidxs[r];
        float4 qv, xv;
        qv.x = Ws[(d4 * 4 + 0) * 512 + k];  xv.x = Xs[(d4 * 4 + 0) * 256 + r];
        qv.y = Ws[(d4 * 4 + 1) * 512 + k];  xv.y = Xs[(d4 * 4 + 1) * 256 + r];
        qv.z = Ws[(d4 * 4 + 2) * 512 + k];  xv.z = Xs[(d4 * 4 + 2) * 256 + r];
        qv.w = Ws[(d4 * 4 + 3) * 512 + k];  xv.w = Xs[(d4 * 4 + 3) * 256 + r];
        float* dst = out_q + (row0 + r) * DIM + d4 * 4;
        dst[0] = qv.x;  dst[1] = qv.y;  dst[2] = qv.z;  dst[3] = qv.w;
        float dx = qv.x - xv.x, dy = qv.y - xv.y;
        float dz = qv.z - xv.z, dw = qv.w - xv.w;
        sq += dx * dx + dy * dy + dz * dz + dw * dw;
    }

    redf[tid] = sq;
    __syncthreads();
    #pragma unroll
    for (int s = THREADS / 2; s > 0; s >>= 1) {
        if (tid < s) redf[tid] += redf[tid + s];
        __syncthreads();
    }
    if (tid == 0) g_partials[bid] = redf[0];
}

// ---------------------------------------------------------------------------
// Final: deterministic scalar reductions -> loss, perplexity
// ---------------------------------------------------------------------------
__global__ void vq_final(float* __restrict__ out) {
    __shared__ float sh[KCODES];
    int t = threadIdx.x;

    float p = (float)g_counts[t] * (1.0f / (float)N_ROWS);
    sh[t] = -p * logf(p + 1e-10f);
    __syncthreads();
    for (int s = KCODES / 2; s > 0; s >>= 1) {
        if (t < s) sh[t] += sh[t + s];
        __syncthreads();
    }
    float ent = sh[0];
    __syncthreads();

    float ps = 0.f;
    for (int i = t; i < NCTA; i += KCODES) ps += g_partials[i];
    sh[t] = ps;
    __syncthreads();
    for (int s = KCODES / 2; s > 0; s >>= 1) {
        if (t < s) sh[t] += sh[t + s];
        __syncthreads();
    }
    if (t == 0) {
        float mse = sh[0] / (float)((size_t)N_ROWS * DIM);
        out[0] = 1.25f * mse;                              // q_loss + 0.25*e_loss
        out[1 + (size_t)N_ROWS * DIM] = expf(ent) / (float)KCODES;
    }
}

// ---------------------------------------------------------------------------
extern "C" void kernel_launch(void* const* d_in, const int* in_sizes, int n_in,
                              void* d_out, int out_size)
{
    const float* X = (const float*)d_in[0];
    const float* W = (const float*)d_in[1];
    if (n_in >= 2 && in_sizes[0] == KCODES * DIM) {  // defensive input-order check
        X = (const float*)d_in[1];
        W = (const float*)d_in[0];
    }
    float* out = (float*)d_out;
    (void)out_size;

    cudaFuncSetAttribute(vq_main, cudaFuncAttributeMaxDynamicSharedMemorySize,
                         SMEM_BYTES);

    vq_prep<<<1, KCODES>>>();
    vq_main<<<NCTA, THREADS, SMEM_BYTES>>>(X, W, out);
    vq_final<<<1, KCODES>>>(out);
}